// round 10
// baseline (speedup 1.0000x reference)
#include <cuda_runtime.h>
#include <cuda_bf16.h>
#include <cstdint>

#define FULLMASK 0xffffffffu

// Given the pair {a,b} and one selected member m, recover the other member
// bitwise: other = a ^ b ^ m. Single LOP3 on the ALU pipe (vs a second FMNMX
// on the FMA pipe) -> balances the two rt=2 pipes for ~1 CE/cycle/SMSP.
__device__ __forceinline__ float xor_other(float a, float b, float m) {
    return __int_as_float(__float_as_int(a) ^ __float_as_int(b) ^ __float_as_int(m));
}

// Compile-time-direction compare-exchange. DESC: a (lower index) gets max.
template<bool DESC>
__device__ __forceinline__ void ce_ct(float& a, float& b) {
    float mn = fminf(a, b);
    float mx = xor_other(a, b, mn);
    if (DESC) { a = mx; b = mn; } else { a = mn; b = mx; }
}

// In-register pass: distance J < 32 (register-index bit). Element index is
// idx = lane*32 + r. Direction bit (idx & K): for K < 32 it is a register bit
// (compile-time); for K >= 32 it is a lane bit (runtime, uniform per lane).
template<int K, int J>
__device__ __forceinline__ void pass_reg(float (&v)[32], int lane) {
    if constexpr (K < 32) {
        #pragma unroll
        for (int r = 0; r < 32; r++) {
            if ((r & J) == 0) {
                if ((r & K) == 0) ce_ct<true >(v[r], v[r | J]);
                else              ce_ct<false>(v[r], v[r | J]);
            }
        }
    } else {
        const bool down = ((lane & (K >> 5)) == 0);
        #pragma unroll
        for (int r = 0; r < 32; r++) {
            if ((r & J) == 0) {
                float a = v[r], b = v[r | J];
                float mn = fminf(a, b);
                float mx = xor_other(a, b, mn);
                v[r]     = down ? mx : mn;
                v[r | J] = down ? mn : mx;
            }
        }
    }
}

// Cross-lane pass: distance J >= 32 -> shfl.xor with lane mask J>>5.
// Lane with (lane & mask)==0 plays the "i" role (lower element index).
template<int K, int J>
__device__ __forceinline__ void pass_shfl(float (&v)[32], int lane) {
    constexpr int MASK = J >> 5;
    const bool down     = ((lane & (K >> 5)) == 0);
    const bool keep_max = (down == ((lane & MASK) == 0));
    #pragma unroll
    for (int r = 0; r < 32; r++) {
        float p  = __shfl_xor_sync(FULLMASK, v[r], MASK);
        float mn = fminf(v[r], p);
        float mx = xor_other(v[r], p, mn);
        v[r] = keep_max ? mx : mn;
    }
}

template<int K, int J>
__device__ __forceinline__ void merge_steps(float (&v)[32], int lane) {
    if constexpr (J >= 32) pass_shfl<K, J>(v, lane);
    else                   pass_reg <K, J>(v, lane);
    if constexpr (J > 1) merge_steps<K, (J >> 1)>(v, lane);
}

// Full bitonic sort (descending) over 1024 elements held as 32 regs x 32 lanes.
template<int K>
__device__ __forceinline__ void bitonic_stage(float (&v)[32], int lane) {
    merge_steps<K, (K >> 1)>(v, lane);
    if constexpr (K < 1024) bitonic_stage<(K << 1)>(v, lane);
}

__global__ void GlobalRankPooling_kernel(const float* __restrict__ x,
                                         const float* __restrict__ w,
                                         const float* __restrict__ bias,
                                         float* __restrict__ out,
                                         int C, int rows) {
    const int lane = threadIdx.x & 31;
    const int row  = blockIdx.x * (blockDim.x >> 5) + (threadIdx.x >> 5);
    if (row >= rows) return;
    const int c = row % C;

    // ---- Load: fully coalesced float4. Initial placement is irrelevant
    // (the sort only cares about the multiset of values).
    float v[32];
    const float4* xp = reinterpret_cast<const float4*>(x) + (size_t)row * 256;
    #pragma unroll
    for (int i = 0; i < 8; i++) {
        float4 t = xp[i * 32 + lane];
        v[4 * i + 0] = t.x; v[4 * i + 1] = t.y;
        v[4 * i + 2] = t.z; v[4 * i + 3] = t.w;
    }

    // ---- Sort descending: after this, v[r] on `lane` = sorted_desc[lane*32 + r].
    bitonic_stage<2>(v, lane);

    // ---- Dot with weight row in sorted-rank order. Each lane reads its own
    // 128B line (lane*32 floats) -> perfect L1 line reuse across the 8 loads;
    // the 8MB weight tensor stays L2-resident across the 32 batches.
    const float4* wp = reinterpret_cast<const float4*>(w) + (size_t)c * 256 + lane * 8;
    float acc = 0.0f;
    #pragma unroll
    for (int i = 0; i < 8; i++) {
        float4 t = wp[i];
        acc += t.x * v[4 * i + 0] + t.y * v[4 * i + 1]
             + t.z * v[4 * i + 2] + t.w * v[4 * i + 3];
    }

    // ---- Warp reduce + bias.
    #pragma unroll
    for (int m = 16; m; m >>= 1) acc += __shfl_xor_sync(FULLMASK, acc, m);
    if (lane == 0) out[row] = acc + __ldg(bias + c);
}

extern "C" void kernel_launch(void* const* d_in, const int* in_sizes, int n_in,
                              void* d_out, int out_size) {
    const float* x    = (const float*)d_in[0];   // (B, C, H, W) fp32
    const float* w    = (const float*)d_in[1];   // (C, 1, S)    fp32
    const float* bias = (const float*)d_in[2];   // (C,)         fp32
    float* out = (float*)d_out;                  // (B, C, 1)    fp32

    const int C    = in_sizes[2];                // 2048
    const int rows = in_sizes[0] / 1024;         // B*C = 65536 (S = 1024)

    const int warps_per_block = 8;               // 256 threads
    const int blocks = (rows + warps_per_block - 1) / warps_per_block;
    GlobalRankPooling_kernel<<<blocks, 256>>>(x, w, bias, out, C, rows);
}

// round 11
// speedup vs baseline: 1.4024x; 1.4024x over previous
#include <cuda_runtime.h>
#include <cuda_bf16.h>
#include <cstdint>

#define FULLMASK 0xffffffffu

// ---------------------------------------------------------------------------
// Compare-exchange building blocks.
//
// `down ? fmaxf(a,b) : fminf(a,b)` is the ptxas idiom for a single predicated
// FMNMX (alu pipe, 1 instr). Two variants per CE:
//   - 2-FMNMX:  2 alu ops
//   - arithmetic: s=a+b (FADD, fma pipe), lo=FMNMX (alu), hi=s-lo (FADD, fma)
//     -> 1 alu + 2 fma ops
// Mixing them 1/3 : 2/3 co-saturates the alu pipe, fma pipe and issue slots.
// ---------------------------------------------------------------------------

// In-register pass: distance J < 32 (register-index bit). Element index is
// idx = lane*32 + r. Direction bit (idx & K): for K < 32 it's a register bit
// (compile-time constant after unroll); for K >= 32 it's a lane bit (runtime,
// uniform across the whole pass).
template<int K, int J>
__device__ __forceinline__ void pass_reg(float (&v)[32], int lane) {
    const bool down_rt = ((lane & (K >> 5)) == 0);   // only meaningful K>=32
    #pragma unroll
    for (int r = 0; r < 32; r++) {
        if ((r & J) == 0) {
            const bool down = (K < 32) ? ((r & K) == 0) : down_rt;
            float a = v[r], b = v[r | J];
            if ((r % 3) != 0) {
                // arithmetic variant (2/3 of CEs): offload to fma pipe
                float s  = a + b;                                   // FADD (fma)
                float lo = down ? fmaxf(a, b) : fminf(a, b);        // FMNMX pred (alu)
                v[r]     = lo;
                v[r | J] = s - lo;                                  // FADD (fma)
            } else {
                // pure FMNMX variant (1/3 of CEs)
                v[r]     = down ? fmaxf(a, b) : fminf(a, b);        // FMNMX pred
                v[r | J] = down ? fminf(a, b) : fmaxf(a, b);        // FMNMX !pred
            }
        }
    }
}

// Cross-lane pass: distance J >= 32 -> shfl.xor with lane mask J>>5.
// Each element keeps exactly one of {min,max}; selection is a single
// predicated FMNMX (predicate uniform across the pass).
template<int K, int J>
__device__ __forceinline__ void pass_shfl(float (&v)[32], int lane) {
    constexpr int MASK = J >> 5;
    const bool down     = ((lane & (K >> 5)) == 0);
    const bool keep_max = (down == ((lane & MASK) == 0));
    #pragma unroll
    for (int r = 0; r < 32; r++) {
        float p = __shfl_xor_sync(FULLMASK, v[r], MASK);
        v[r] = keep_max ? fmaxf(v[r], p) : fminf(v[r], p);          // FMNMX pred
    }
}

template<int K, int J>
__device__ __forceinline__ void merge_steps(float (&v)[32], int lane) {
    if constexpr (J >= 32) pass_shfl<K, J>(v, lane);
    else                   pass_reg <K, J>(v, lane);
    if constexpr (J > 1) merge_steps<K, (J >> 1)>(v, lane);
}

// Full bitonic sort (descending) over 1024 elements held as 32 regs x 32 lanes.
template<int K>
__device__ __forceinline__ void bitonic_stage(float (&v)[32], int lane) {
    merge_steps<K, (K >> 1)>(v, lane);
    if constexpr (K < 1024) bitonic_stage<(K << 1)>(v, lane);
}

__global__ void GlobalRankPooling_kernel(const float* __restrict__ x,
                                         const float* __restrict__ w,
                                         const float* __restrict__ bias,
                                         float* __restrict__ out,
                                         int C, int rows) {
    const int lane = threadIdx.x & 31;
    const int row  = blockIdx.x * (blockDim.x >> 5) + (threadIdx.x >> 5);
    if (row >= rows) return;
    const int c = row % C;

    // ---- Load: fully coalesced float4. Initial placement is irrelevant
    // (the sort only cares about the multiset of values).
    float v[32];
    const float4* xp = reinterpret_cast<const float4*>(x) + (size_t)row * 256;
    #pragma unroll
    for (int i = 0; i < 8; i++) {
        float4 t = xp[i * 32 + lane];
        v[4 * i + 0] = t.x; v[4 * i + 1] = t.y;
        v[4 * i + 2] = t.z; v[4 * i + 3] = t.w;
    }

    // ---- Sort descending: after this, v[r] on `lane` = sorted_desc[lane*32 + r].
    bitonic_stage<2>(v, lane);

    // ---- Dot with weight row in sorted-rank order. Each lane reads its own
    // 128B line (lane*32 floats); the 8MB weight tensor stays L2-resident
    // across the 32 batches.
    const float4* wp = reinterpret_cast<const float4*>(w) + (size_t)c * 256 + lane * 8;
    float acc = 0.0f;
    #pragma unroll
    for (int i = 0; i < 8; i++) {
        float4 t = wp[i];
        acc += t.x * v[4 * i + 0] + t.y * v[4 * i + 1]
             + t.z * v[4 * i + 2] + t.w * v[4 * i + 3];
    }

    // ---- Warp reduce + bias.
    #pragma unroll
    for (int m = 16; m; m >>= 1) acc += __shfl_xor_sync(FULLMASK, acc, m);
    if (lane == 0) out[row] = acc + __ldg(bias + c);
}

extern "C" void kernel_launch(void* const* d_in, const int* in_sizes, int n_in,
                              void* d_out, int out_size) {
    const float* x    = (const float*)d_in[0];   // (B, C, H, W) fp32
    const float* w    = (const float*)d_in[1];   // (C, 1, S)    fp32
    const float* bias = (const float*)d_in[2];   // (C,)         fp32
    float* out = (float*)d_out;                  // (B, C, 1)    fp32

    const int C    = in_sizes[2];                // 2048
    const int rows = in_sizes[0] / 1024;         // B*C = 65536 (S = 1024)

    const int warps_per_block = 8;               // 256 threads
    const int blocks = (rows + warps_per_block - 1) / warps_per_block;
    GlobalRankPooling_kernel<<<blocks, 256>>>(x, w, bias, out, C, rows);
}